// round 8
// baseline (speedup 1.0000x reference)
#include <cuda_runtime.h>

#define B_    64
#define C_    768
#define HW_   784      // 28*28
#define HID_  192      // C/4
#define HW4_  196      // HW/4

#define NB_   148      // persistent grid (all resident: 1 block/SM, <=152 SMs)
#define NT_   1024
#define NWARPS_ (NB_ * (NT_/32))          // 4736
#define NTHREADS_ ((unsigned)NB_ * NT_)   // 151552

#define NCH_  4
#define BPC_  (B_ / NCH_)                      // 16 batches per chunk (38.5 MB of x)
#define ROWS_PER_CHUNK (BPC_ * C_)             // 12288 (b,c) rows
#define F4_PER_CHUNK   (ROWS_PER_CHUNK * HW4_) // 2,408,448 float4
#define PAIRS_PER_CHUNK (F4_PER_CHUNK / 2)     // 1,204,224

// scratch (no device allocation allowed)
__device__ float g_pooled[B_ * C_];
__device__ float g_s[B_ * C_];
__device__ unsigned g_bar_arrive;   // zero-init; returns to 0 after every barrier
__device__ unsigned g_bar_gen;      // monotone generation counter (wrap-safe)

// ---------------------------------------------------------------------------
// Software grid barrier. Safe because grid == NB_ blocks are all guaranteed
// concurrently resident. Deterministic across graph replays: arrive resets to
// 0 each barrier; gen is compared by equality (monotone, wrap-free semantics).
// ---------------------------------------------------------------------------
__device__ __forceinline__ void grid_bar() {
    __syncthreads();
    if (threadIdx.x == 0) {
        __threadfence();                                   // publish my writes
        unsigned gen = *(volatile unsigned*)&g_bar_gen;    // read BEFORE arriving
        unsigned v = atomicAdd(&g_bar_arrive, 1u);
        if (v == NB_ - 1u) {
            g_bar_arrive = 0u;
            __threadfence();
            atomicAdd(&g_bar_gen, 1u);                     // release
        } else {
            while (*(volatile unsigned*)&g_bar_gen == gen) __nanosleep(64);
        }
        __threadfence();                                   // acquire
    }
    __syncthreads();
}

// ---------------------------------------------------------------------------
// One persistent kernel. Per chunk of 16 batches:
//   pool (reads 38.5 MB of x from DRAM -> L2-resident)
//   grid_bar
//   fc   (block-per-batch: fc1 + fc2 with block-local syncs)
//   grid_bar
//   scale (rereads the same 38.5 MB from L2, writes out to DRAM)
// then straight into next chunk's pool (natural overlap with straggler scale).
// ---------------------------------------------------------------------------
__global__ void __launch_bounds__(NT_, 1)
hse_persistent(const float* __restrict__ x,
               const float* __restrict__ w1, const float* __restrict__ b1,
               const float* __restrict__ w2, const float* __restrict__ b2,
               float* __restrict__ out)
{
    __shared__ float sp[C_];
    __shared__ float sh[HID_];

    const unsigned tid   = threadIdx.x;
    const unsigned lane  = tid & 31u;
    const unsigned wid   = tid >> 5;
    const unsigned gwarp = blockIdx.x * (NT_ / 32) + wid;
    const float4* xp = reinterpret_cast<const float4*>(x);
    float4*       op = reinterpret_cast<float4*>(out);

    for (int ch = 0; ch < NCH_; ch++) {
        // ================= pool: warp per (b,c) row =================
        const unsigned row_base = (unsigned)ch * ROWS_PER_CHUNK;
        for (unsigned r = gwarp; r < ROWS_PER_CHUNK; r += NWARPS_) {
            const float4* p = xp + (size_t)(row_base + r) * HW4_;
            float4 a0 = p[lane];
            float4 a1 = p[lane + 32];
            float4 a2 = p[lane + 64];
            float4 a3 = p[lane + 96];
            float4 a4 = p[lane + 128];
            float4 a5 = p[lane + 160];
            float extra = 0.f;
            if (lane < 4) {                       // indices 192..195
                float4 v = p[lane + 192];
                extra = (v.x + v.y) + (v.z + v.w);
            }
            float s01 = (a0.x + a0.y) + (a0.z + a0.w) + (a1.x + a1.y) + (a1.z + a1.w);
            float s23 = (a2.x + a2.y) + (a2.z + a2.w) + (a3.x + a3.y) + (a3.z + a3.w);
            float s45 = (a4.x + a4.y) + (a4.z + a4.w) + (a5.x + a5.y) + (a5.z + a5.w);
            float sum = (s01 + s23) + (s45 + extra);
            #pragma unroll
            for (int o = 16; o > 0; o >>= 1)
                sum += __shfl_xor_sync(0xffffffffu, sum, o);
            if (lane == 0)
                g_pooled[row_base + r] = sum * (1.0f / HW_);
        }
        grid_bar();

        // ================= fc: block-per-batch (blocks 0..BPC_-1) =================
        if (blockIdx.x < BPC_) {
            const int b = ch * BPC_ + (int)blockIdx.x;
            for (unsigned i = tid; i < C_; i += NT_)
                sp[i] = g_pooled[b * C_ + i];
            __syncthreads();

            // fc1: warp per h output (32 warps x 6 outputs)
            for (unsigned h = wid; h < HID_; h += 32) {
                const float4* wv = reinterpret_cast<const float4*>(w1 + h * C_);
                const float4* pv = reinterpret_cast<const float4*>(sp);
                float acc = 0.f;
                #pragma unroll
                for (int k = 0; k < 6; k++) {
                    float4 a = pv[lane + 32 * k];
                    float4 w = wv[lane + 32 * k];
                    acc += a.x * w.x + a.y * w.y + a.z * w.z + a.w * w.w;
                }
                #pragma unroll
                for (int o = 16; o > 0; o >>= 1)
                    acc += __shfl_xor_sync(0xffffffffu, acc, o);
                if (lane == 0)
                    sh[h] = fmaxf(acc + b1[h], 0.f);
            }
            __syncthreads();

            // fc2: warp per c output (32 warps x 24 outputs)
            for (unsigned c = wid; c < C_; c += 32) {
                const float4* wv = reinterpret_cast<const float4*>(w2 + c * HID_);
                const float4* hv = reinterpret_cast<const float4*>(sh);
                float4 a = hv[lane];
                float4 w = wv[lane];
                float acc = a.x * w.x + a.y * w.y + a.z * w.z + a.w * w.w;
                if (lane < 16) {
                    a = hv[lane + 32];
                    w = wv[lane + 32];
                    acc += a.x * w.x + a.y * w.y + a.z * w.z + a.w * w.w;
                }
                #pragma unroll
                for (int o = 16; o > 0; o >>= 1)
                    acc += __shfl_xor_sync(0xffffffffu, acc, o);
                if (lane == 0)
                    g_s[b * C_ + c] = __saturatef((acc + b2[c]) * (1.0f / 6.0f) + 0.5f);
            }
        }
        grid_bar();

        // ================= scale: out = x * s, x read hits L2 =================
        const unsigned f4base = (unsigned)ch * F4_PER_CHUNK;
        const unsigned t0 = blockIdx.x * NT_ + tid;
        for (unsigned j = t0; j < PAIRS_PER_CHUNK; j += NTHREADS_) {
            unsigned f0 = f4base + 2u * j;
            float s = g_s[f0 / HW4_];          // HW4_ even -> pair in one channel
            float4 v0 = __ldcs(xp + f0);       // last use (still hits L2)
            float4 v1 = __ldcs(xp + f0 + 1);
            v0.x *= s; v0.y *= s; v0.z *= s; v0.w *= s;
            v1.x *= s; v1.y *= s; v1.z *= s; v1.w *= s;
            __stcs(op + f0,     v0);           // evict-first: protect next chunk
            __stcs(op + f0 + 1, v1);
        }
        // no barrier: next pool touches disjoint state; fc(ch+1) is fenced by
        // the post-pool barrier which every block reaches only after its scale.
    }
}

// ---------------------------------------------------------------------------
extern "C" void kernel_launch(void* const* d_in, const int* in_sizes, int n_in,
                              void* d_out, int out_size) {
    const float* x  = (const float*)d_in[0];
    const float* w1 = (const float*)d_in[1];
    const float* b1 = (const float*)d_in[2];
    const float* w2 = (const float*)d_in[3];
    const float* b2 = (const float*)d_in[4];
    float* out = (float*)d_out;

    hse_persistent<<<NB_, NT_>>>(x, w1, b1, w2, b2, out);
}